// round 7
// baseline (speedup 1.0000x reference)
#include <cuda_runtime.h>
#include <cuda_bf16.h>
#include <math.h>

#define BB   64
#define LL   65536
#define NW   2047
#define WPB  128
#define BPB  16
#define SPAN_MAX 4128
#define HID  512
#define DM   256
#define SD   321

// ---------------- scratch (__device__ globals; no allocation allowed) -------
__device__ unsigned int g_hist_parts[BB * BPB * 256];
__device__ float g_went[BB * NW];
__device__ float g_feats[BB * SD];
__device__ float g_z1p[2][BB * HID];
__device__ float g_z2p[2][BB * HID];
__device__ float g_outp[4][BB * DM];
__device__ float g_a2[BB * HID];
__device__ float g_a3[BB * HID];
__device__ unsigned int g_bar;

// ---------------- Kernel A: windowed entropies + global hist partials -------
__global__ void __launch_bounds__(256) win_kernel(const int* __restrict__ x) {
    const int b    = blockIdx.y;
    const int blk  = blockIdx.x;
    const int tid  = threadIdx.x;
    const int lane = tid & 31;
    const int warp = tid >> 5;

    if (blk == 0 && b == 0 && tid == 0) g_bar = 0u;   // reset MLP grid barrier

    const int wstart = blk * WPB;
    const int wcount = min(WPB, NW - wstart);
    const int span   = (wcount - 1) * 32 + 64;
    const long base  = (long)b * LL + (long)blk * (WPB * 32);

    __shared__ __align__(16) unsigned char s_x[SPAN_MAX + 32];
    __shared__ unsigned int  s_hist[8][64];   // packed u8 counts (4 per word)
    __shared__ unsigned int  s_part[256];
    __shared__ float         s_lut[65];

    if (tid < 256) s_part[tid] = 0u;
    if (tid <= 64) {
        if (tid == 0) s_lut[0] = 0.0f;
        else {
            float p = (float)tid * (1.0f / 64.0f);
            float t = -(p * log2f(p + 1e-10f));
            s_lut[tid] = t / (float)tid;
        }
    }
    {
        const int4* xv = (const int4*)(x + base);
        uchar4* sv = (uchar4*)s_x;
        const int n4 = span >> 2;
        for (int i = tid; i < n4; i += 256) {
            int4 v = xv[i];
            sv[i] = make_uchar4((unsigned char)min(max(v.x, 0), 255),
                                (unsigned char)min(max(v.y, 0), 255),
                                (unsigned char)min(max(v.z, 0), 255),
                                (unsigned char)min(max(v.w, 0), 255));
        }
    }
    __syncthreads();

    for (int i = tid; i < 4096; i += 256)
        atomicAdd(&s_part[s_x[i]], 1u);

    unsigned int* hist = s_hist[warp];
    for (int wi = warp; wi < wcount; wi += 8) {
        const int off = wi * 32;
        hist[lane]      = 0u;
        hist[lane + 32] = 0u;
        __syncwarp();
        const int va = s_x[off + lane];
        const int vb = s_x[off + 32 + lane];
        atomicAdd(&hist[va >> 2], 1u << ((va & 3) << 3));
        atomicAdd(&hist[vb >> 2], 1u << ((vb & 3) << 3));
        __syncwarp();
        const unsigned ca = (hist[va >> 2] >> ((va & 3) << 3)) & 0xFFu;
        const unsigned cb = (hist[vb >> 2] >> ((vb & 3) << 3)) & 0xFFu;
        float h = s_lut[ca] + s_lut[cb];
        #pragma unroll
        for (int o = 16; o; o >>= 1) h += __shfl_xor_sync(0xffffffffu, h, o);
        if (lane == 0) g_went[b * NW + wstart + wi] = h;
    }

    __syncthreads();
    if (tid < 256) g_hist_parts[(b * BPB + blk) * 256 + tid] = s_part[tid];
}

// ---------------- fused feat + MLP persistent kernel -------------------------
__device__ __forceinline__ void grid_sync(unsigned int target) {
    __syncthreads();
    if (threadIdx.x == 0) {
        __threadfence();                       // release our writes
        atomicAdd(&g_bar, 1u);
        volatile unsigned int* p = &g_bar;
        while (*p < target) { __nanosleep(64); }
        __threadfence();                       // acquire (L1 invalidate)
    }
    __syncthreads();
}

__shared__ float s_w[64][128];
__shared__ float s_a[64][10];

// GEMM phase: 64 jobs. Tile 8 rows x 128 cols, split-K.
// MODE 1: A=g_feats K=321 N=512 ksplit2 x 3 chunks -> g_z1p
// MODE 2: A=g_a2   K=512 N=512 ksplit2 x 4 chunks -> g_z2p
// MODE 3: A=g_a3   K=512 N=256 ksplit4 x 2 chunks -> g_outp
template <int MODE>
__device__ void gemm_phase(const float* __restrict__ W) {
    constexpr int N      = (MODE == 3) ? DM : HID;
    constexpr int K      = (MODE == 1) ? SD : HID;
    constexpr int CHUNKS = (MODE == 1) ? 3 : ((MODE == 2) ? 4 : 2);

    const int job = blockIdx.x;
    int ct, rg, ks;
    if (MODE == 3) { ct = job & 1; rg = (job >> 1) & 7; ks = job >> 4; }
    else           { ct = job & 3; rg = (job >> 2) & 7; ks = job >> 5; }
    const int c0 = ct * 128, r0 = rg * 8;
    const int kbase = ks * (CHUNKS * 64);

    const float* A  = (MODE == 1) ? g_feats : ((MODE == 2) ? g_a2 : g_a3);
    const int astr  = (MODE == 1) ? SD : HID;

    const int tid = threadIdx.x;
    const int rp = tid >> 6, cp = tid & 63;

    float a00 = 0.f, a01 = 0.f, a10 = 0.f, a11 = 0.f;
    for (int c = 0; c < CHUNKS; c++) {
        const int k0 = kbase + c * 64;
        {
            const int kr0 = tid >> 5, c4 = (tid & 31) * 4;
            #pragma unroll
            for (int i = 0; i < 8; i++) {
                const int kr = kr0 + i * 8;
                float4 v = make_float4(0.f, 0.f, 0.f, 0.f);
                if (MODE != 1 || (k0 + kr) < K)
                    v = *(const float4*)&W[(long)(k0 + kr) * N + c0 + c4];
                *(float4*)&s_w[kr][c4] = v;
            }
        }
        for (int i = tid; i < 512; i += 256) {
            const int r = i >> 6, k = i & 63;
            float v = 0.f;
            if (MODE != 1 || (k0 + k) < K) v = A[(r0 + r) * astr + k0 + k];
            s_a[k][r] = v;
        }
        __syncthreads();
        #pragma unroll 8
        for (int kk = 0; kk < 64; kk++) {
            const float2 wv = *(const float2*)&s_w[kk][cp * 2];
            const float2 av = *(const float2*)&s_a[kk][rp * 2];
            a00 = fmaf(av.x, wv.x, a00);
            a01 = fmaf(av.x, wv.y, a01);
            a10 = fmaf(av.y, wv.x, a10);
            a11 = fmaf(av.y, wv.y, a11);
        }
        __syncthreads();
    }

    float* OP = (MODE == 1) ? &g_z1p[0][0] : ((MODE == 2) ? &g_z2p[0][0] : &g_outp[0][0]);
    const long base = (long)ks * (BB * N);
    const int r = r0 + rp * 2, cc = c0 + cp * 2;
    *(float2*)&OP[base + (long)r * N + cc]       = make_float2(a00, a01);
    *(float2*)&OP[base + (long)(r + 1) * N + cc] = make_float2(a10, a11);
}

// LN phase: block = row. 256 threads, 2 features each. SP=2 partials.
template <int LAYER>
__device__ void ln_phase(const float* __restrict__ bias,
                         const float* __restrict__ gam,
                         const float* __restrict__ bet) {
    const float* P = (LAYER == 1) ? &g_z1p[0][0] : &g_z2p[0][0];
    float* outA    = (LAYER == 1) ? g_a2 : g_a3;

    const int r    = blockIdx.x;
    const int tid  = threadIdx.x;
    const int lane = tid & 31;
    const int wid  = tid >> 5;
    const int k1 = tid, k2 = tid + 256;

    __shared__ float s_r[8];
    __shared__ float s_tot;

    float z1 = bias[k1] + P[r * HID + k1] + P[BB * HID + r * HID + k1];
    float z2 = bias[k2] + P[r * HID + k2] + P[BB * HID + r * HID + k2];

    float t = z1 + z2;
    #pragma unroll
    for (int o = 16; o; o >>= 1) t += __shfl_xor_sync(0xffffffffu, t, o);
    if (lane == 0) s_r[wid] = t;
    __syncthreads();
    if (tid == 0) {
        float u = 0.f;
        #pragma unroll
        for (int i = 0; i < 8; i++) u += s_r[i];
        s_tot = u;
    }
    __syncthreads();
    const float mu = s_tot * (1.0f / 512.0f);

    const float d1 = z1 - mu, d2 = z2 - mu;
    float v = d1 * d1 + d2 * d2;
    #pragma unroll
    for (int o = 16; o; o >>= 1) v += __shfl_xor_sync(0xffffffffu, v, o);
    if (lane == 0) s_r[wid] = v;
    __syncthreads();
    if (tid == 0) {
        float u = 0.f;
        #pragma unroll
        for (int i = 0; i < 8; i++) u += s_r[i];
        s_tot = u;
    }
    __syncthreads();
    const float rstd = rsqrtf(s_tot * (1.0f / 512.0f) + 1e-5f);

    outA[r * HID + k1] = fmaxf(d1 * rstd * gam[k1] + bet[k1], 0.0f);
    outA[r * HID + k2] = fmaxf(d2 * rstd * gam[k2] + bet[k2], 0.0f);
}

__global__ void __launch_bounds__(256) mlp_fused_kernel(
    const float* __restrict__ W1, const float* __restrict__ b1,
    const float* __restrict__ g1, const float* __restrict__ be1,
    const float* __restrict__ W2, const float* __restrict__ b2,
    const float* __restrict__ g2, const float* __restrict__ be2,
    const float* __restrict__ W3, const float* __restrict__ b3,
    float* __restrict__ out) {
    const int b = blockIdx.x;
    const int tid = threadIdx.x;

    // ---- phase A: features (one block per batch row) ----
    {
        __shared__ float        s_red[256];
        __shared__ float        s_lev[64];
        __shared__ unsigned int s_cnt[64];

        float term = 0.0f;
        {
            unsigned int c = 0;
            #pragma unroll
            for (int p = 0; p < BPB; p++)
                c += g_hist_parts[(b * BPB + p) * 256 + tid];
            float nh = (float)c * (1.0f / 65536.0f);
            g_feats[b * SD + tid] = nh;
            term = -(nh * log2f(nh + 1e-10f));
        }
        s_red[tid] = term;
        if (tid < 64) {
            s_lev[tid] = (tid == 63) ? 8.0f : (float)tid * (8.0f / 63.0f);
            s_cnt[tid] = 0u;
        }
        __syncthreads();
        for (int s = 128; s; s >>= 1) {
            if (tid < s) s_red[tid] += s_red[tid + s];
            __syncthreads();
        }
        if (tid == 0) g_feats[b * SD + 256] = s_red[0];

        for (int i = tid; i < NW; i += 256) {
            float h = g_went[b * NW + i];
            int lo = 0, hi = 63;
            while (lo < hi) {
                int mid = (lo + hi) >> 1;
                if (h <= s_lev[mid]) hi = mid; else lo = mid + 1;
            }
            atomicAdd(&s_cnt[lo], 1u);
        }
        __syncthreads();
        if (tid < 64) {
            unsigned int sum = 0;
            for (int k = 0; k <= tid; k++) sum += s_cnt[k];
            g_feats[b * SD + 257 + tid] = (float)sum / 2047.0f;
        }
    }

    grid_sync(64);
    gemm_phase<1>(W1);
    grid_sync(128);
    ln_phase<1>(b1, g1, be1);
    grid_sync(192);
    gemm_phase<2>(W2);
    grid_sync(256);
    ln_phase<2>(b2, g2, be2);
    grid_sync(320);
    gemm_phase<3>(W3);
    grid_sync(384);

    // ---- phase G: out = sum(g_outp) + b3 ----
    {
        const int i = blockIdx.x * 256 + tid;
        float v = b3[i & (DM - 1)];
        #pragma unroll
        for (int s = 0; s < 4; s++) v += g_outp[s][i];
        out[i] = v;
    }
}

// ---------------- launch ----------------------------------------------------
extern "C" void kernel_launch(void* const* d_in, const int* in_sizes, int n_in,
                              void* d_out, int out_size) {
    const int*   x   = (const int*)d_in[0];
    const float* W1  = (const float*)d_in[1];
    const float* b1  = (const float*)d_in[2];
    const float* g1  = (const float*)d_in[3];
    const float* be1 = (const float*)d_in[4];
    const float* W2  = (const float*)d_in[5];
    const float* b2  = (const float*)d_in[6];
    const float* g2  = (const float*)d_in[7];
    const float* be2 = (const float*)d_in[8];
    const float* W3  = (const float*)d_in[9];
    const float* b3  = (const float*)d_in[10];
    float* out = (float*)d_out;

    win_kernel<<<dim3(BPB, BB), 256>>>(x);
    mlp_fused_kernel<<<BB, 256>>>(W1, b1, g1, be1, W2, b2, g2, be2, W3, b3, out);
}

// round 8
// speedup vs baseline: 1.3495x; 1.3495x over previous
#include <cuda_runtime.h>
#include <cuda_bf16.h>
#include <math.h>

#define BB   64
#define LL   65536
#define NW   2047
#define WPB  128
#define BPB  16
#define SPAN_MAX 4128
#define HID  512
#define DM   256
#define SD   321

#define GRID2 128
#define SMEM2 72704   // 64KB W tile + 5KB A tile + slack

// ---------------- scratch (__device__ globals; no allocation allowed) -------
__device__ unsigned int g_hist_parts[BB * BPB * 256];
__device__ float g_went[BB * NW];
__device__ float g_feats[BB * SD];
__device__ float g_z1p[4][BB * HID];
__device__ float g_z2p[4][BB * HID];
__device__ float g_outp[8][BB * DM];
__device__ float g_a2[BB * HID];
__device__ float g_a3[BB * HID];
__device__ float g_sink;
__device__ unsigned int g_bar;

// ---------------- Kernel A: windowed entropies + global hist partials -------
__global__ void __launch_bounds__(256) win_kernel(const int* __restrict__ x) {
    const int b    = blockIdx.y;
    const int blk  = blockIdx.x;
    const int tid  = threadIdx.x;
    const int lane = tid & 31;
    const int warp = tid >> 5;

    if (blk == 0 && b == 0 && tid == 0) g_bar = 0u;   // reset grid barrier

    const int wstart = blk * WPB;
    const int wcount = min(WPB, NW - wstart);
    const int span   = (wcount - 1) * 32 + 64;
    const long base  = (long)b * LL + (long)blk * (WPB * 32);

    __shared__ __align__(16) unsigned char s_x[SPAN_MAX + 32];
    __shared__ unsigned int  s_hist[8][64];
    __shared__ unsigned int  s_part[256];
    __shared__ float         s_lut[65];

    if (tid < 256) s_part[tid] = 0u;
    if (tid <= 64) {
        if (tid == 0) s_lut[0] = 0.0f;
        else {
            float p = (float)tid * (1.0f / 64.0f);
            float t = -(p * log2f(p + 1e-10f));
            s_lut[tid] = t / (float)tid;
        }
    }
    {
        const int4* xv = (const int4*)(x + base);
        uchar4* sv = (uchar4*)s_x;
        const int n4 = span >> 2;
        for (int i = tid; i < n4; i += 256) {
            int4 v = xv[i];
            sv[i] = make_uchar4((unsigned char)min(max(v.x, 0), 255),
                                (unsigned char)min(max(v.y, 0), 255),
                                (unsigned char)min(max(v.z, 0), 255),
                                (unsigned char)min(max(v.w, 0), 255));
        }
    }
    __syncthreads();

    for (int i = tid; i < 4096; i += 256)
        atomicAdd(&s_part[s_x[i]], 1u);

    unsigned int* hist = s_hist[warp];
    for (int wi = warp; wi < wcount; wi += 8) {
        const int off = wi * 32;
        hist[lane]      = 0u;
        hist[lane + 32] = 0u;
        __syncwarp();
        const int va = s_x[off + lane];
        const int vb = s_x[off + 32 + lane];
        atomicAdd(&hist[va >> 2], 1u << ((va & 3) << 3));
        atomicAdd(&hist[vb >> 2], 1u << ((vb & 3) << 3));
        __syncwarp();
        const unsigned ca = (hist[va >> 2] >> ((va & 3) << 3)) & 0xFFu;
        const unsigned cb = (hist[vb >> 2] >> ((vb & 3) << 3)) & 0xFFu;
        float h = s_lut[ca] + s_lut[cb];
        #pragma unroll
        for (int o = 16; o; o >>= 1) h += __shfl_xor_sync(0xffffffffu, h, o);
        if (lane == 0) g_went[b * NW + wstart + wi] = h;
    }

    __syncthreads();
    if (tid < 256) g_hist_parts[(b * BPB + blk) * 256 + tid] = s_part[tid];
}

// ---------------- persistent fused feat + MLP --------------------------------
__device__ __forceinline__ void grid_sync(unsigned int target) {
    __syncthreads();
    if (threadIdx.x == 0) {
        __threadfence();
        atomicAdd(&g_bar, 1u);
        volatile unsigned int* p = &g_bar;
        while (*p < target) {}
        __threadfence();
    }
    __syncthreads();
}

// One 8r x 128c x CH-k job per block. 128 jobs per layer.
// MODE 1: A=g_feats K=321 CH=96  ks(4) -> g_z1p
// MODE 2: A=g_a2   K=512 CH=128 ks(4) -> g_z2p
// MODE 3: A=g_a3   K=512 CH=64  ks(8) -> g_outp (N=256)
template <int MODE>
__device__ void gemm_phase(const float* __restrict__ W, char* smem) {
    constexpr int CH = (MODE == 1) ? 96 : ((MODE == 2) ? 128 : 64);
    constexpr int N  = (MODE == 3) ? DM : HID;
    constexpr int K  = (MODE == 1) ? SD : HID;

    const int job = blockIdx.x;
    int ct, rg, ks;
    if (MODE == 3) { ct = job & 1; rg = (job >> 1) & 7; ks = job >> 4; }
    else           { ct = job & 3; rg = (job >> 2) & 7; ks = job >> 5; }
    const int c0 = ct * 128, r0 = rg * 8, k0 = ks * CH;

    float* s_w = (float*)smem;                       // [CH][128]
    float* s_a = (float*)(smem + CH * 128 * 4);      // [CH][10]

    const int tid = threadIdx.x;

    // W tile: CH x 128, coalesced float4
    {
        const int kr0 = tid >> 5, c4 = (tid & 31) * 4;
        #pragma unroll
        for (int i = 0; i < CH / 8; i++) {
            const int kr = kr0 + i * 8;
            float4 v = make_float4(0.f, 0.f, 0.f, 0.f);
            if (MODE != 1 || (k0 + kr) < K)
                v = *(const float4*)&W[(long)(k0 + kr) * N + c0 + c4];
            *(float4*)&s_w[kr * 128 + c4] = v;
        }
    }
    // A tile: 8 rows x CH k, transposed
    {
        const float* A = (MODE == 1) ? g_feats : ((MODE == 2) ? g_a2 : g_a3);
        const int astr = (MODE == 1) ? SD : HID;
        #pragma unroll
        for (int it = 0; it < (8 * CH) / 256; it++) {
            const int idx = tid + it * 256;
            const int r = idx / CH, k = idx - r * CH;
            float v = 0.f;
            if (MODE != 1 || (k0 + k) < K) v = A[(r0 + r) * astr + k0 + k];
            s_a[k * 10 + r] = v;
        }
    }
    __syncthreads();

    const int rp = tid >> 6, cp = tid & 63;
    float a00 = 0.f, a01 = 0.f, a10 = 0.f, a11 = 0.f;
    #pragma unroll 8
    for (int kk = 0; kk < CH; kk++) {
        const float2 wv = *(const float2*)&s_w[kk * 128 + cp * 2];
        const float2 av = *(const float2*)&s_a[kk * 10 + rp * 2];
        a00 = fmaf(av.x, wv.x, a00);
        a01 = fmaf(av.x, wv.y, a01);
        a10 = fmaf(av.y, wv.x, a10);
        a11 = fmaf(av.y, wv.y, a11);
    }

    float* OP = (MODE == 1) ? &g_z1p[0][0] : ((MODE == 2) ? &g_z2p[0][0] : &g_outp[0][0]);
    const long base = (long)ks * (BB * N);
    const int r = r0 + rp * 2, cc = c0 + cp * 2;
    *(float2*)&OP[base + (long)r * N + cc]       = make_float2(a00, a01);
    *(float2*)&OP[base + (long)(r + 1) * N + cc] = make_float2(a10, a11);
}

// LN phase: block = row (first 64 blocks). 256 threads, 2 features each.
template <int LAYER>
__device__ void ln_phase(const float* __restrict__ bias,
                         const float* __restrict__ gam,
                         const float* __restrict__ bet, char* smem) {
    const float* P = (LAYER == 1) ? &g_z1p[0][0] : &g_z2p[0][0];
    float* outA    = (LAYER == 1) ? g_a2 : g_a3;
    float* s_r     = (float*)smem;      // [8]
    float* s_tot   = s_r + 8;

    const int r    = blockIdx.x;
    const int tid  = threadIdx.x;
    const int lane = tid & 31;
    const int wid  = tid >> 5;
    const int k1 = tid, k2 = tid + 256;

    float z1 = bias[k1], z2 = bias[k2];
    #pragma unroll
    for (int s = 0; s < 4; s++) {
        z1 += P[(long)s * (BB * HID) + r * HID + k1];
        z2 += P[(long)s * (BB * HID) + r * HID + k2];
    }

    float t = z1 + z2;
    #pragma unroll
    for (int o = 16; o; o >>= 1) t += __shfl_xor_sync(0xffffffffu, t, o);
    if (lane == 0) s_r[wid] = t;
    __syncthreads();
    if (tid == 0) {
        float u = 0.f;
        #pragma unroll
        for (int i = 0; i < 8; i++) u += s_r[i];
        *s_tot = u;
    }
    __syncthreads();
    const float mu = *s_tot * (1.0f / 512.0f);

    const float d1 = z1 - mu, d2 = z2 - mu;
    float v = d1 * d1 + d2 * d2;
    #pragma unroll
    for (int o = 16; o; o >>= 1) v += __shfl_xor_sync(0xffffffffu, v, o);
    if (lane == 0) s_r[wid] = v;
    __syncthreads();
    if (tid == 0) {
        float u = 0.f;
        #pragma unroll
        for (int i = 0; i < 8; i++) u += s_r[i];
        *s_tot = u;
    }
    __syncthreads();
    const float rstd = rsqrtf(*s_tot * (1.0f / 512.0f) + 1e-5f);

    outA[r * HID + k1] = fmaxf(d1 * rstd * gam[k1] + bet[k1], 0.0f);
    outA[r * HID + k2] = fmaxf(d2 * rstd * gam[k2] + bet[k2], 0.0f);
}

__global__ void __launch_bounds__(256, 1) mlp_fused2(
    const float* __restrict__ W1, const float* __restrict__ b1,
    const float* __restrict__ g1, const float* __restrict__ be1,
    const float* __restrict__ W2, const float* __restrict__ b2,
    const float* __restrict__ g2, const float* __restrict__ be2,
    const float* __restrict__ W3, const float* __restrict__ b3,
    float* __restrict__ out) {
    extern __shared__ __align__(16) char smem[];
    const int job = blockIdx.x;
    const int tid = threadIdx.x;

    // ---- phase A: features (blocks 0-63); blocks 64-127 prefetch weights ----
    if (job < BB) {
        const int b = job;
        float* s_red = (float*)smem;             // [256]
        float* s_lev = s_red + 256;              // [64]
        unsigned int* s_cnt = (unsigned int*)(s_lev + 64);  // [64]

        float term = 0.0f;
        {
            unsigned int c = 0;
            #pragma unroll
            for (int p = 0; p < BPB; p++)
                c += g_hist_parts[(b * BPB + p) * 256 + tid];
            float nh = (float)c * (1.0f / 65536.0f);
            g_feats[b * SD + tid] = nh;
            term = -(nh * log2f(nh + 1e-10f));
        }
        s_red[tid] = term;
        if (tid < 64) {
            s_lev[tid] = (tid == 63) ? 8.0f : (float)tid * (8.0f / 63.0f);
            s_cnt[tid] = 0u;
        }
        __syncthreads();
        for (int s = 128; s; s >>= 1) {
            if (tid < s) s_red[tid] += s_red[tid + s];
            __syncthreads();
        }
        if (tid == 0) g_feats[b * SD + 256] = s_red[0];

        for (int i = tid; i < NW; i += 256) {
            float h = g_went[b * NW + i];
            int lo = 0, hi = 63;
            while (lo < hi) {
                int mid = (lo + hi) >> 1;
                if (h <= s_lev[mid]) hi = mid; else lo = mid + 1;
            }
            atomicAdd(&s_cnt[lo], 1u);
        }
        __syncthreads();
        if (tid < 64) {
            unsigned int sum = 0;
            for (int k = 0; k <= tid; k++) sum += s_cnt[k];
            g_feats[b * SD + 257 + tid] = (float)sum / 2047.0f;
        }
    } else {
        // warm L2 with all three weight matrices
        const int tg = (job - BB) * 256 + tid;   // 0..16383
        float acc = 0.f;
        const int n1 = (SD * HID) / 4 + 1, n2 = (HID * HID) / 4, n3 = (HID * DM) / 4;
        for (int i = tg; i < n1 - 1; i += BB * 256) {
            float4 v = *(const float4*)&W1[i * 4];
            acc += v.x + v.y + v.z + v.w;
        }
        for (int i = tg; i < n2; i += BB * 256) {
            float4 v = *(const float4*)&W2[i * 4];
            acc += v.x + v.y + v.z + v.w;
        }
        for (int i = tg; i < n3; i += BB * 256) {
            float4 v = *(const float4*)&W3[i * 4];
            acc += v.x + v.y + v.z + v.w;
        }
        if (__float_as_uint(acc) == 0xdeadbeefu) g_sink = acc;
    }

    grid_sync(1 * GRID2);
    gemm_phase<1>(W1, smem);
    grid_sync(2 * GRID2);
    if (job < BB) ln_phase<1>(b1, g1, be1, smem);
    grid_sync(3 * GRID2);
    gemm_phase<2>(W2, smem);
    grid_sync(4 * GRID2);
    if (job < BB) ln_phase<2>(b2, g2, be2, smem);
    grid_sync(5 * GRID2);
    gemm_phase<3>(W3, smem);
    grid_sync(6 * GRID2);

    // ---- finalize: out = sum(g_outp) + b3 (blocks 0-63) ----
    if (job < BB) {
        const int i = job * 256 + tid;
        float v = b3[i & (DM - 1)];
        #pragma unroll
        for (int s = 0; s < 8; s++) v += g_outp[s][i];
        out[i] = v;
    }
}

// ---------------- launch ----------------------------------------------------
extern "C" void kernel_launch(void* const* d_in, const int* in_sizes, int n_in,
                              void* d_out, int out_size) {
    const int*   x   = (const int*)d_in[0];
    const float* W1  = (const float*)d_in[1];
    const float* b1  = (const float*)d_in[2];
    const float* g1  = (const float*)d_in[3];
    const float* be1 = (const float*)d_in[4];
    const float* W2  = (const float*)d_in[5];
    const float* b2  = (const float*)d_in[6];
    const float* g2  = (const float*)d_in[7];
    const float* be2 = (const float*)d_in[8];
    const float* W3  = (const float*)d_in[9];
    const float* b3  = (const float*)d_in[10];
    float* out = (float*)d_out;

    cudaFuncSetAttribute(mlp_fused2, cudaFuncAttributeMaxDynamicSharedMemorySize, SMEM2);

    win_kernel<<<dim3(BPB, BB), 256>>>(x);
    mlp_fused2<<<GRID2, 256, SMEM2>>>(W1, b1, g1, be1, W2, b2, g2, be2, W3, b3, out);
}